// round 3
// baseline (speedup 1.0000x reference)
#include <cuda_runtime.h>
#include <cuda_bf16.h>
#include <cstdint>

// Problem constants
#define BATCH 8
#define DIM 256
#define NTOK 1024           // H*W = 32*32
#define NHEADS 8
#define DHEAD 32            // DIM_HEAD / NUM_HEADS
#define QKV_ROWS 768        // 3 * DIM_HEAD
#define SCALE 0.17677669529663687f   // 32^-0.5
#define NEG_INF __int_as_float(0xff800000)

// Scratch (device globals — no runtime allocation allowed)
__device__ float g_qkv[BATCH * QKV_ROWS * NTOK];  // [b][o][n], o = t*256 + h*32 + d
__device__ float g_o[BATCH * DIM * NTOK];         // [b][c][n], c = h*32 + d

// ---------------------------------------------------------------------------
// Tiled fp32 GEMM: C[b] = A (MxK) * B[b] (KxN) (+ bias), A shared over batch.
// Block tile 64x128, K-step 16, 256 threads, 4x8 micro-tile per thread.
// ---------------------------------------------------------------------------
#define BM 64
#define BN 128
#define BKK 16

template <bool BIAS>
__global__ __launch_bounds__(256) void gemm_bias_kernel(
    const float* __restrict__ A, const float* __restrict__ Bg,
    const float* __restrict__ bias, float* __restrict__ Cg,
    int M, int N, int K)
{
    const float* B = Bg + (size_t)blockIdx.z * K * N;
    float* C = Cg + (size_t)blockIdx.z * M * N;
    const int m0 = blockIdx.y * BM;
    const int n0 = blockIdx.x * BN;

    __shared__ __align__(16) float As[BKK][BM + 1];
    __shared__ __align__(16) float Bs[BKK][BN];

    const int tid = threadIdx.x;
    const int ty = tid >> 4;      // 0..15 -> 4 rows each
    const int tx = tid & 15;      // 0..15 -> 8 cols each

    float acc[4][8];
#pragma unroll
    for (int i = 0; i < 4; i++)
#pragma unroll
        for (int j = 0; j < 8; j++) acc[i][j] = 0.f;

    for (int k0 = 0; k0 < K; k0 += BKK) {
        // A tile: BM x BKK, stored transposed As[k][m]
#pragma unroll
        for (int t = 0; t < (BM * BKK) / 256; t++) {
            int idx = tid + t * 256;
            int r = idx >> 4;        // 0..63
            int c = idx & 15;        // 0..15
            As[c][r] = A[(size_t)(m0 + r) * K + k0 + c];
        }
        // B tile: BKK x BN
#pragma unroll
        for (int t = 0; t < (BKK * BN) / 256; t++) {
            int idx = tid + t * 256;
            int r = idx >> 7;        // 0..15
            int c = idx & 127;       // 0..127
            Bs[r][c] = B[(size_t)(k0 + r) * N + n0 + c];
        }
        __syncthreads();

#pragma unroll
        for (int k = 0; k < BKK; k++) {
            float a[4];
#pragma unroll
            for (int mm = 0; mm < 4; mm++) a[mm] = As[k][ty * 4 + mm];
            float4 b0 = *(const float4*)&Bs[k][tx * 8];
            float4 b1 = *(const float4*)&Bs[k][tx * 8 + 4];
            float b[8] = {b0.x, b0.y, b0.z, b0.w, b1.x, b1.y, b1.z, b1.w};
#pragma unroll
            for (int mm = 0; mm < 4; mm++)
#pragma unroll
                for (int nn = 0; nn < 8; nn++)
                    acc[mm][nn] += a[mm] * b[nn];
        }
        __syncthreads();
    }

#pragma unroll
    for (int mm = 0; mm < 4; mm++) {
        int row = m0 + ty * 4 + mm;
        float bv = BIAS ? bias[row] : 0.f;
        float4 o0 = make_float4(acc[mm][0] + bv, acc[mm][1] + bv,
                                acc[mm][2] + bv, acc[mm][3] + bv);
        float4 o1 = make_float4(acc[mm][4] + bv, acc[mm][5] + bv,
                                acc[mm][6] + bv, acc[mm][7] + bv);
        float* cp = &C[(size_t)row * N + n0 + tx * 8];
        *(float4*)cp = o0;
        *(float4*)(cp + 4) = o1;
    }
}

// ---------------------------------------------------------------------------
// Fused flash attention, fp32. One thread per query (d=32 in registers).
// K/V tiles of JT=128 tokens staged in smem as [j][d] (pad 36 -> 16B aligned
// rows, float4 broadcast reads in the inner loops). Chunked online softmax.
// Grid: (qtiles=8, heads=8, batch=8), 128 threads.
// ---------------------------------------------------------------------------
#define JT 128
#define CH 16

__global__ __launch_bounds__(128, 4) void attn_kernel(
    const float* __restrict__ qkv, float* __restrict__ O)
{
    const int b = blockIdx.z;
    const int h = blockIdx.y;
    const int i = blockIdx.x * 128 + threadIdx.x;   // query token

    const float* qb = qkv + ((size_t)b * QKV_ROWS + h * DHEAD) * NTOK;
    const float* kb = qb + (size_t)256 * NTOK;
    const float* vb = qb + (size_t)512 * NTOK;

    __shared__ __align__(16) float Ks[JT][36];
    __shared__ __align__(16) float Vs[JT][36];

    float q[DHEAD];
#pragma unroll
    for (int d = 0; d < DHEAD; d++) q[d] = qb[(size_t)d * NTOK + i] * SCALE;

    float o[DHEAD];
#pragma unroll
    for (int d = 0; d < DHEAD; d++) o[d] = 0.f;
    float m = NEG_INF;
    float l = 0.f;

    for (int j0 = 0; j0 < NTOK; j0 += JT) {
        // stage K/V tile transposed: Ks[j][d]
#pragma unroll
        for (int t = 0; t < (JT * DHEAD) / 128; t++) {
            int idx = threadIdx.x + t * 128;
            int d = idx >> 7;       // idx / JT
            int j = idx & 127;      // idx % JT
            Ks[j][d] = kb[(size_t)d * NTOK + j0 + j];
            Vs[j][d] = vb[(size_t)d * NTOK + j0 + j];
        }
        __syncthreads();

#pragma unroll
        for (int c = 0; c < JT / CH; c++) {
            float sc[CH];
            float cmax = NEG_INF;
#pragma unroll
            for (int jj = 0; jj < CH; jj++) {
                const float4* kp = (const float4*)&Ks[c * CH + jj][0];
                float s0 = 0.f, s1 = 0.f, s2 = 0.f, s3 = 0.f;
#pragma unroll
                for (int d4 = 0; d4 < 8; d4++) {
                    float4 kv = kp[d4];
                    s0 += q[d4 * 4 + 0] * kv.x;
                    s1 += q[d4 * 4 + 1] * kv.y;
                    s2 += q[d4 * 4 + 2] * kv.z;
                    s3 += q[d4 * 4 + 3] * kv.w;
                }
                float s = (s0 + s1) + (s2 + s3);
                sc[jj] = s;
                cmax = fmaxf(cmax, s);
            }
            float mn = fmaxf(m, cmax);
            float alpha = __expf(m - mn);   // exp(-inf)=0 on first chunk
            m = mn;
            l *= alpha;
#pragma unroll
            for (int d = 0; d < DHEAD; d++) o[d] *= alpha;
#pragma unroll
            for (int jj = 0; jj < CH; jj++) {
                float p = __expf(sc[jj] - m);
                l += p;
                const float4* vp = (const float4*)&Vs[c * CH + jj][0];
#pragma unroll
                for (int d4 = 0; d4 < 8; d4++) {
                    float4 vv = vp[d4];
                    o[d4 * 4 + 0] += p * vv.x;
                    o[d4 * 4 + 1] += p * vv.y;
                    o[d4 * 4 + 2] += p * vv.z;
                    o[d4 * 4 + 3] += p * vv.w;
                }
            }
        }
        __syncthreads();
    }

    const float inv = 1.f / l;
    float* op = O + ((size_t)b * DIM + h * DHEAD) * NTOK + i;
#pragma unroll
    for (int d = 0; d < DHEAD; d++) op[(size_t)d * NTOK] = o[d] * inv;
}

// ---------------------------------------------------------------------------
// Launch
// ---------------------------------------------------------------------------
extern "C" void kernel_launch(void* const* d_in, const int* in_sizes, int n_in,
                              void* d_out, int out_size)
{
    const float* x = nullptr;      // 8*256*32*32 = 2097152
    const float* w_qkv = nullptr;  // 768*256     = 196608
    const float* w_out = nullptr;  // 256*256     = 65536
    const float* b_out = nullptr;  // 256
    for (int idx = 0; idx < n_in; idx++) {
        switch (in_sizes[idx]) {
            case 2097152: x = (const float*)d_in[idx]; break;
            case 196608:  w_qkv = (const float*)d_in[idx]; break;
            case 65536:   w_out = (const float*)d_in[idx]; break;
            case 256:     b_out = (const float*)d_in[idx]; break;
            default: break;
        }
    }
    float* out = (float*)d_out;

    float* qkvp = nullptr;
    float* op = nullptr;
    cudaGetSymbolAddress((void**)&qkvp, g_qkv);
    cudaGetSymbolAddress((void**)&op, g_o);

    // 1) QKV projection: [768,256] x [256,1024] per batch
    {
        dim3 grid(NTOK / BN, QKV_ROWS / BM, BATCH);
        gemm_bias_kernel<false><<<grid, 256>>>(w_qkv, x, nullptr, qkvp,
                                               QKV_ROWS, NTOK, DIM);
    }
    // 2) Fused attention
    {
        dim3 grid(NTOK / 128, NHEADS, BATCH);
        attn_kernel<<<grid, 128>>>(qkvp, op);
    }
    // 3) Output projection + bias: [256,256] x [256,1024] per batch
    {
        dim3 grid(NTOK / BN, DIM / BM, BATCH);
        gemm_bias_kernel<true><<<grid, 256>>>(w_out, op, b_out, out,
                                              DIM, NTOK, DIM);
    }
}

// round 4
// speedup vs baseline: 3.3175x; 3.3175x over previous
#include <cuda_runtime.h>
#include <cuda_bf16.h>
#include <cstdint>

#define BATCH 8
#define DIM 256
#define NTOK 1024
#define NHEADS 8
#define DHEAD 32
#define QKV_ROWS 768
#define SCALE 0.17677669529663687f
#define NEG_INF __int_as_float(0xff800000)

// Scratch (device globals — no runtime allocation allowed)
__device__ float g_qkv[BATCH * QKV_ROWS * NTOK];  // [b][o][n], o = t*256 + h*32 + d
__device__ float g_o[BATCH * DIM * NTOK];         // [b][c][n], c = h*32 + d

// ---------------------------------------------------------------------------
// tf32 helpers
// ---------------------------------------------------------------------------
__device__ __forceinline__ uint32_t f2tf(float x) {
    uint32_t r;
    asm("cvt.rna.tf32.f32 %0, %1;" : "=r"(r) : "f"(x));
    return r;
}
__device__ __forceinline__ float f2tf_f(float x) { return __uint_as_float(f2tf(x)); }

__device__ __forceinline__ void mma_tf32(float c[4], const uint32_t a[4],
                                         uint32_t b0, uint32_t b1) {
    asm volatile(
        "mma.sync.aligned.m16n8k8.row.col.f32.tf32.tf32.f32 "
        "{%0,%1,%2,%3},{%4,%5,%6,%7},{%8,%9},{%0,%1,%2,%3};"
        : "+f"(c[0]), "+f"(c[1]), "+f"(c[2]), "+f"(c[3])
        : "r"(a[0]), "r"(a[1]), "r"(a[2]), "r"(a[3]), "r"(b0), "r"(b1));
}

// ---------------------------------------------------------------------------
// tf32 GEMM: C[b] = A (MxK) * B[b] (KxN) (+ bias). CTA tile 128x128, kstep 32.
// 8 warps as 4x2; warp tile 32x64 (2 mtiles x 8 ntiles of m16n8).
// ---------------------------------------------------------------------------
template <bool BIAS>
__global__ __launch_bounds__(256) void gemm_tf32_kernel(
    const float* __restrict__ A, const float* __restrict__ Bg,
    const float* __restrict__ bias, float* __restrict__ Cg,
    int M, int N, int K)
{
    const float* B = Bg + (size_t)blockIdx.z * K * N;
    float* C = Cg + (size_t)blockIdx.z * M * N;
    const int m0 = blockIdx.y * 128;
    const int n0 = blockIdx.x * 128;

    __shared__ float As[128][36];   // [m][k], pad 4
    __shared__ float Bs[32][132];   // [k][n], pad 4

    const int tid = threadIdx.x;
    const int lane = tid & 31;
    const int wid = tid >> 5;
    const int wm = wid >> 1;       // 0..3
    const int wn = wid & 1;        // 0..1
    const int g = lane >> 2;       // group id 0..7
    const int q = lane & 3;        // thread-in-group

    float c[2][8][4];
#pragma unroll
    for (int mt = 0; mt < 2; mt++)
#pragma unroll
        for (int nt = 0; nt < 8; nt++)
#pragma unroll
            for (int e = 0; e < 4; e++) c[mt][nt][e] = 0.f;

    for (int k0 = 0; k0 < K; k0 += 32) {
        // A tile 128x32: 1024 float4
#pragma unroll
        for (int t = 0; t < 4; t++) {
            int f = tid + t * 256;
            int r = f >> 3;
            int c4 = (f & 7) * 4;
            float4 v = *(const float4*)&A[(size_t)(m0 + r) * K + k0 + c4];
            As[r][c4 + 0] = f2tf_f(v.x);
            As[r][c4 + 1] = f2tf_f(v.y);
            As[r][c4 + 2] = f2tf_f(v.z);
            As[r][c4 + 3] = f2tf_f(v.w);
        }
        // B tile 32x128
#pragma unroll
        for (int t = 0; t < 4; t++) {
            int f = tid + t * 256;
            int r = f >> 5;
            int c4 = (f & 31) * 4;
            float4 v = *(const float4*)&B[(size_t)(k0 + r) * N + n0 + c4];
            Bs[r][c4 + 0] = f2tf_f(v.x);
            Bs[r][c4 + 1] = f2tf_f(v.y);
            Bs[r][c4 + 2] = f2tf_f(v.z);
            Bs[r][c4 + 3] = f2tf_f(v.w);
        }
        __syncthreads();

#pragma unroll
        for (int ks = 0; ks < 4; ks++) {
            const int kk = ks * 8;
            uint32_t a[2][4];
#pragma unroll
            for (int mt = 0; mt < 2; mt++) {
                int row = wm * 32 + mt * 16 + g;
                a[mt][0] = __float_as_uint(As[row][kk + q]);
                a[mt][1] = __float_as_uint(As[row + 8][kk + q]);
                a[mt][2] = __float_as_uint(As[row][kk + q + 4]);
                a[mt][3] = __float_as_uint(As[row + 8][kk + q + 4]);
            }
#pragma unroll
            for (int nt = 0; nt < 8; nt++) {
                int col = wn * 64 + nt * 8 + g;
                uint32_t b0 = __float_as_uint(Bs[kk + q][col]);
                uint32_t b1 = __float_as_uint(Bs[kk + q + 4][col]);
                mma_tf32(c[0][nt], a[0], b0, b1);
                mma_tf32(c[1][nt], a[1], b0, b1);
            }
        }
        __syncthreads();
    }

#pragma unroll
    for (int mt = 0; mt < 2; mt++) {
        int row = m0 + wm * 32 + mt * 16 + g;
        float bv0 = BIAS ? bias[row] : 0.f;
        float bv8 = BIAS ? bias[row + 8] : 0.f;
#pragma unroll
        for (int nt = 0; nt < 8; nt++) {
            int col = n0 + wn * 64 + nt * 8 + 2 * q;
            float2 lo = make_float2(c[mt][nt][0] + bv0, c[mt][nt][1] + bv0);
            float2 hi = make_float2(c[mt][nt][2] + bv8, c[mt][nt][3] + bv8);
            *(float2*)&C[(size_t)row * N + col] = lo;
            *(float2*)&C[(size_t)(row + 8) * N + col] = hi;
        }
    }
}

// ---------------------------------------------------------------------------
// Flash attention with tf32 mma. CTA = (qtile of 128, head, batch), 8 warps,
// each warp owns 16 queries. K/V j-tiles of 128 in smem ([d][j], tf32).
// S = Q*K^T via mma (Q pre-scaled, in registers for whole kernel);
// fp32 online softmax on C fragments; P->A fragment relayout via shuffles;
// out^T accumulated as A=P (16 x j), B=V^T (j x d).
// ---------------------------------------------------------------------------
__global__ __launch_bounds__(256) void attn_mma_kernel(
    const float* __restrict__ qkv, float* __restrict__ O)
{
    const int b = blockIdx.z;
    const int h = blockIdx.y;

    const float* qb = qkv + ((size_t)b * QKV_ROWS + h * DHEAD) * NTOK;
    const float* kb = qb + (size_t)256 * NTOK;
    const float* vb = qb + (size_t)512 * NTOK;

    __shared__ float Ks[32][132];
    __shared__ float Vs[32][132];

    const int tid = threadIdx.x;
    const int lane = tid & 31;
    const int wid = tid >> 5;
    const int g = lane >> 2;
    const int q = lane & 3;
    const int iw = blockIdx.x * 128 + wid * 16;   // warp query base

    // Q fragments (A, row-major): rows = queries, cols = d. Pre-scaled.
    uint32_t qa[4][4];
#pragma unroll
    for (int ks = 0; ks < 4; ks++) {
        qa[ks][0] = f2tf(qb[(size_t)(ks * 8 + q) * NTOK + iw + g] * SCALE);
        qa[ks][1] = f2tf(qb[(size_t)(ks * 8 + q) * NTOK + iw + 8 + g] * SCALE);
        qa[ks][2] = f2tf(qb[(size_t)(ks * 8 + q + 4) * NTOK + iw + g] * SCALE);
        qa[ks][3] = f2tf(qb[(size_t)(ks * 8 + q + 4) * NTOK + iw + 8 + g] * SCALE);
    }

    float m0 = NEG_INF, m1 = NEG_INF, l0 = 0.f, l1 = 0.f;
    float oc[4][4];
#pragma unroll
    for (int dn = 0; dn < 4; dn++)
#pragma unroll
        for (int e = 0; e < 4; e++) oc[dn][e] = 0.f;

    for (int j0 = 0; j0 < NTOK; j0 += 128) {
        // stage K,V tiles (32 x 128 each), converted to tf32
#pragma unroll
        for (int t = 0; t < 4; t++) {
            int f = tid + t * 256;
            int r = f >> 5;
            int c4 = (f & 31) * 4;
            float4 kv = *(const float4*)&kb[(size_t)r * NTOK + j0 + c4];
            Ks[r][c4 + 0] = f2tf_f(kv.x);
            Ks[r][c4 + 1] = f2tf_f(kv.y);
            Ks[r][c4 + 2] = f2tf_f(kv.z);
            Ks[r][c4 + 3] = f2tf_f(kv.w);
            float4 vv = *(const float4*)&vb[(size_t)r * NTOK + j0 + c4];
            Vs[r][c4 + 0] = f2tf_f(vv.x);
            Vs[r][c4 + 1] = f2tf_f(vv.y);
            Vs[r][c4 + 2] = f2tf_f(vv.z);
            Vs[r][c4 + 3] = f2tf_f(vv.w);
        }
        __syncthreads();

        // S = Q * K^T : 16 n-tiles of 8 j's
        float s[16][4];
#pragma unroll
        for (int nt = 0; nt < 16; nt++) {
            s[nt][0] = 0.f; s[nt][1] = 0.f; s[nt][2] = 0.f; s[nt][3] = 0.f;
#pragma unroll
            for (int ks = 0; ks < 4; ks++) {
                uint32_t b0 = __float_as_uint(Ks[ks * 8 + q][nt * 8 + g]);
                uint32_t b1 = __float_as_uint(Ks[ks * 8 + q + 4][nt * 8 + g]);
                mma_tf32(s[nt], qa[ks], b0, b1);
            }
        }

        // Online softmax. Rows: r0 = g (c0,c1), r1 = g+8 (c2,c3).
        float tm0 = NEG_INF, tm1 = NEG_INF;
#pragma unroll
        for (int nt = 0; nt < 16; nt++) {
            tm0 = fmaxf(tm0, fmaxf(s[nt][0], s[nt][1]));
            tm1 = fmaxf(tm1, fmaxf(s[nt][2], s[nt][3]));
        }
        tm0 = fmaxf(tm0, __shfl_xor_sync(0xffffffffu, tm0, 1));
        tm0 = fmaxf(tm0, __shfl_xor_sync(0xffffffffu, tm0, 2));
        tm1 = fmaxf(tm1, __shfl_xor_sync(0xffffffffu, tm1, 1));
        tm1 = fmaxf(tm1, __shfl_xor_sync(0xffffffffu, tm1, 2));

        float mn0 = fmaxf(m0, tm0);
        float mn1 = fmaxf(m1, tm1);
        float al0 = __expf(m0 - mn0);
        float al1 = __expf(m1 - mn1);
        m0 = mn0; m1 = mn1;

        float rs0 = 0.f, rs1 = 0.f;
#pragma unroll
        for (int nt = 0; nt < 16; nt++) {
            s[nt][0] = __expf(s[nt][0] - m0); rs0 += s[nt][0];
            s[nt][1] = __expf(s[nt][1] - m0); rs0 += s[nt][1];
            s[nt][2] = __expf(s[nt][2] - m1); rs1 += s[nt][2];
            s[nt][3] = __expf(s[nt][3] - m1); rs1 += s[nt][3];
        }
        rs0 += __shfl_xor_sync(0xffffffffu, rs0, 1);
        rs0 += __shfl_xor_sync(0xffffffffu, rs0, 2);
        rs1 += __shfl_xor_sync(0xffffffffu, rs1, 1);
        rs1 += __shfl_xor_sync(0xffffffffu, rs1, 2);
        l0 = l0 * al0 + rs0;
        l1 = l1 * al1 + rs1;

#pragma unroll
        for (int dn = 0; dn < 4; dn++) {
            oc[dn][0] *= al0; oc[dn][1] *= al0;
            oc[dn][2] *= al1; oc[dn][3] *= al1;
        }

        // PV: A = P (16 x 8 per kc), B = V^T slice (8 x 8 per dn)
        const int s1 = (lane & ~3) | (q >> 1);
        const int s2 = s1 + 2;
        const bool odd = (q & 1) != 0;
#pragma unroll
        for (int kc = 0; kc < 16; kc++) {
            // C-fragment (cols 2q,2q+1) -> A-fragment (cols q, q+4)
            float t0 = __shfl_sync(0xffffffffu, s[kc][0], s1);
            float t1 = __shfl_sync(0xffffffffu, s[kc][1], s1);
            float t2 = __shfl_sync(0xffffffffu, s[kc][2], s1);
            float t3 = __shfl_sync(0xffffffffu, s[kc][3], s1);
            float u0 = __shfl_sync(0xffffffffu, s[kc][0], s2);
            float u1 = __shfl_sync(0xffffffffu, s[kc][1], s2);
            float u2 = __shfl_sync(0xffffffffu, s[kc][2], s2);
            float u3 = __shfl_sync(0xffffffffu, s[kc][3], s2);
            uint32_t pa[4];
            pa[0] = f2tf(odd ? t1 : t0);
            pa[1] = f2tf(odd ? t3 : t2);
            pa[2] = f2tf(odd ? u1 : u0);
            pa[3] = f2tf(odd ? u3 : u2);
#pragma unroll
            for (int dn = 0; dn < 4; dn++) {
                uint32_t b0 = __float_as_uint(Vs[dn * 8 + g][kc * 8 + q]);
                uint32_t b1 = __float_as_uint(Vs[dn * 8 + g][kc * 8 + q + 4]);
                mma_tf32(oc[dn], pa, b0, b1);
            }
        }
        __syncthreads();
    }

    const float inv0 = 1.f / l0;
    const float inv1 = 1.f / l1;
    // oc[dn] fragment: rows = queries (iw+g, iw+8+g), cols = d (dn*8 + 2q, +1)
#pragma unroll
    for (int dn = 0; dn < 4; dn++) {
        size_t base = ((size_t)b * DIM + h * DHEAD + dn * 8 + 2 * q) * NTOK;
        O[base + iw + g]              = oc[dn][0] * inv0;
        O[base + NTOK + iw + g]       = oc[dn][1] * inv0;
        O[base + iw + 8 + g]          = oc[dn][2] * inv1;
        O[base + NTOK + iw + 8 + g]   = oc[dn][3] * inv1;
    }
}

// ---------------------------------------------------------------------------
// Launch
// ---------------------------------------------------------------------------
extern "C" void kernel_launch(void* const* d_in, const int* in_sizes, int n_in,
                              void* d_out, int out_size)
{
    const float* x = nullptr;      // 2097152
    const float* w_qkv = nullptr;  // 196608
    const float* w_out = nullptr;  // 65536
    const float* b_out = nullptr;  // 256
    for (int idx = 0; idx < n_in; idx++) {
        switch (in_sizes[idx]) {
            case 2097152: x = (const float*)d_in[idx]; break;
            case 196608:  w_qkv = (const float*)d_in[idx]; break;
            case 65536:   w_out = (const float*)d_in[idx]; break;
            case 256:     b_out = (const float*)d_in[idx]; break;
            default: break;
        }
    }
    float* out = (float*)d_out;

    float* qkvp = nullptr;
    float* op = nullptr;
    cudaGetSymbolAddress((void**)&qkvp, g_qkv);
    cudaGetSymbolAddress((void**)&op, g_o);

    // 1) QKV projection: [768,256] x [256,1024] per batch
    {
        dim3 grid(NTOK / 128, QKV_ROWS / 128, BATCH);
        gemm_tf32_kernel<false><<<grid, 256>>>(w_qkv, x, nullptr, qkvp,
                                               QKV_ROWS, NTOK, DIM);
    }
    // 2) Fused flash attention (tf32 mma)
    {
        dim3 grid(NTOK / 128, NHEADS, BATCH);
        attn_mma_kernel<<<grid, 256>>>(qkvp, op);
    }
    // 3) Output projection + bias: [256,256] x [256,1024] per batch
    {
        dim3 grid(NTOK / 128, DIM / 128, BATCH);
        gemm_tf32_kernel<true><<<grid, 256>>>(w_out, op, b_out, out,
                                              DIM, NTOK, DIM);
    }
}

// round 6
// speedup vs baseline: 4.7651x; 1.4364x over previous
#include <cuda_runtime.h>
#include <cuda_bf16.h>
#include <cuda_fp16.h>
#include <cstdint>

#define BATCH 8
#define DIM 256
#define NTOK 1024
#define NHEADS 8
#define DHEAD 32
#define QKV_ROWS 768
#define SCALE 0.17677669529663687f
#define LOG2E 1.4426950408889634f
#define NEG_INF __int_as_float(0xff800000)

__device__ float g_qkv[BATCH * QKV_ROWS * NTOK];  // [b][o][n]
__device__ float g_o[BATCH * DIM * NTOK];         // [b][c][n]

// ---------------------------------------------------------------------------
// helpers
// ---------------------------------------------------------------------------
__device__ __forceinline__ uint32_t f2tf(float x) {
    uint32_t r;
    asm("cvt.rna.tf32.f32 %0, %1;" : "=r"(r) : "f"(x));
    return r;
}
__device__ __forceinline__ void mma_tf32(float c[4], const uint32_t a[4],
                                         uint32_t b0, uint32_t b1) {
    asm volatile(
        "mma.sync.aligned.m16n8k8.row.col.f32.tf32.tf32.f32 "
        "{%0,%1,%2,%3},{%4,%5,%6,%7},{%8,%9},{%0,%1,%2,%3};"
        : "+f"(c[0]), "+f"(c[1]), "+f"(c[2]), "+f"(c[3])
        : "r"(a[0]), "r"(a[1]), "r"(a[2]), "r"(a[3]), "r"(b0), "r"(b1));
}
__device__ __forceinline__ void mma_f16(float c[4], const uint32_t a[4],
                                        uint32_t b0, uint32_t b1) {
    asm volatile(
        "mma.sync.aligned.m16n8k16.row.col.f32.f16.f16.f32 "
        "{%0,%1,%2,%3},{%4,%5,%6,%7},{%8,%9},{%0,%1,%2,%3};"
        : "+f"(c[0]), "+f"(c[1]), "+f"(c[2]), "+f"(c[3])
        : "r"(a[0]), "r"(a[1]), "r"(a[2]), "r"(a[3]), "r"(b0), "r"(b1));
}
__device__ __forceinline__ void cp16(void* dst, const void* src) {
    unsigned d = (unsigned)__cvta_generic_to_shared(dst);
    asm volatile("cp.async.cg.shared.global [%0], [%1], 16;" :: "r"(d), "l"(src));
}
__device__ __forceinline__ void cp_commit() {
    asm volatile("cp.async.commit_group;");
}
template <int N>
__device__ __forceinline__ void cp_wait() {
    asm volatile("cp.async.wait_group %0;" :: "n"(N));
}
// pack two fp32 -> f16x2 register (lo in low half, hi in high half)
__device__ __forceinline__ uint32_t packh2(float lo, float hi) {
    uint32_t r;
    asm("cvt.rn.f16x2.f32 %0, %1, %2;" : "=r"(r) : "f"(hi), "f"(lo));
    return r;
}

// ---------------------------------------------------------------------------
// tf32 GEMM: C[b] = A (MxK) * B[b] (KxN) (+bias). CTA 128x128, kstep 16,
// cp.async double-buffered. 8 warps 4x2, warp tile 32x64.
// ---------------------------------------------------------------------------
template <bool BIAS>
__global__ __launch_bounds__(256, 2) void gemm_tf32_kernel(
    const float* __restrict__ A, const float* __restrict__ Bg,
    const float* __restrict__ bias, float* __restrict__ Cg,
    int M, int N, int K)
{
    const float* B = Bg + (size_t)blockIdx.z * K * N;
    float* C = Cg + (size_t)blockIdx.z * M * N;
    const int m0 = blockIdx.y * 128;
    const int n0 = blockIdx.x * 128;

    __shared__ float As[2][128][20];   // [m][k] pad 20
    __shared__ float Bs[2][16][136];   // [k][n] pad 136

    const int tid = threadIdx.x;
    const int lane = tid & 31;
    const int wid = tid >> 5;
    const int wm = wid >> 1;
    const int wn = wid & 1;
    const int g = lane >> 2;
    const int q = lane & 3;

    float c[2][8][4];
#pragma unroll
    for (int mt = 0; mt < 2; mt++)
#pragma unroll
        for (int nt = 0; nt < 8; nt++)
#pragma unroll
            for (int e = 0; e < 4; e++) c[mt][nt][e] = 0.f;

    const int nkt = K / 16;

#define GEMM_STAGE(buf, k0)                                                 \
    {                                                                       \
        _Pragma("unroll")                                                   \
        for (int t = 0; t < 2; t++) {                                       \
            int ch = tid + t * 256;                                         \
            int r = ch >> 2, c4 = (ch & 3) * 4;                             \
            cp16(&As[buf][r][c4], &A[(size_t)(m0 + r) * K + (k0) + c4]);    \
        }                                                                   \
        _Pragma("unroll")                                                   \
        for (int t = 0; t < 2; t++) {                                       \
            int ch = tid + t * 256;                                         \
            int r = ch >> 5, c4 = (ch & 31) * 4;                            \
            cp16(&Bs[buf][r][c4], &B[(size_t)((k0) + r) * N + n0 + c4]);    \
        }                                                                   \
    }

    GEMM_STAGE(0, 0);
    cp_commit();

    for (int kt = 0; kt < nkt; kt++) {
        const int buf = kt & 1;
        if (kt + 1 < nkt) {
            GEMM_STAGE(buf ^ 1, (kt + 1) * 16);
            cp_commit();
            cp_wait<1>();
        } else {
            cp_wait<0>();
        }
        __syncthreads();

#pragma unroll
        for (int ks = 0; ks < 2; ks++) {
            const int kk = ks * 8;
            uint32_t a[2][4];
#pragma unroll
            for (int mt = 0; mt < 2; mt++) {
                int row = wm * 32 + mt * 16 + g;
                a[mt][0] = f2tf(As[buf][row][kk + q]);
                a[mt][1] = f2tf(As[buf][row + 8][kk + q]);
                a[mt][2] = f2tf(As[buf][row][kk + q + 4]);
                a[mt][3] = f2tf(As[buf][row + 8][kk + q + 4]);
            }
#pragma unroll
            for (int nt = 0; nt < 8; nt++) {
                int col = wn * 64 + nt * 8 + g;
                uint32_t b0 = f2tf(Bs[buf][kk + q][col]);
                uint32_t b1 = f2tf(Bs[buf][kk + q + 4][col]);
                mma_tf32(c[0][nt], a[0], b0, b1);
                mma_tf32(c[1][nt], a[1], b0, b1);
            }
        }
        __syncthreads();
    }
#undef GEMM_STAGE

#pragma unroll
    for (int mt = 0; mt < 2; mt++) {
        int row = m0 + wm * 32 + mt * 16 + g;
        float bv0 = BIAS ? bias[row] : 0.f;
        float bv8 = BIAS ? bias[row + 8] : 0.f;
#pragma unroll
        for (int nt = 0; nt < 8; nt++) {
            int col = n0 + wn * 64 + nt * 8 + 2 * q;
            float2 lo = make_float2(c[mt][nt][0] + bv0, c[mt][nt][1] + bv0);
            float2 hi = make_float2(c[mt][nt][2] + bv8, c[mt][nt][3] + bv8);
            *(float2*)&C[(size_t)row * N + col] = lo;
            *(float2*)&C[(size_t)(row + 8) * N + col] = hi;
        }
    }
}

// ---------------------------------------------------------------------------
// Flash attention. CTA = (128-query tile, head, batch), 8 warps x 16 queries.
// j-tiles of 64, K/V raw fp32 double-buffered via cp.async ([d][j], pad 72).
// S: tf32 m16n8k8 (Q prescaled by SCALE*log2e, exp2 softmax).
// PV: fp16 m16n8k16 — S C-fragments convert directly into P A-fragments.
// ---------------------------------------------------------------------------
#define JT 64

__global__ __launch_bounds__(256, 2) void attn_mma_kernel(
    const float* __restrict__ qkv, float* __restrict__ O)
{
    const int b = blockIdx.z;
    const int h = blockIdx.y;

    const float* qb = qkv + ((size_t)b * QKV_ROWS + h * DHEAD) * NTOK;
    const float* kb = qb + (size_t)256 * NTOK;
    const float* vb = qb + (size_t)512 * NTOK;

    __shared__ float Ks[2][32][72];
    __shared__ float Vs[2][32][72];

    const int tid = threadIdx.x;
    const int lane = tid & 31;
    const int wid = tid >> 5;
    const int g = lane >> 2;
    const int q = lane & 3;
    const int iw = blockIdx.x * 128 + wid * 16;

    // Q fragments, prescaled into log2 domain
    const float qs = SCALE * LOG2E;
    uint32_t qa[4][4];
#pragma unroll
    for (int ks = 0; ks < 4; ks++) {
        qa[ks][0] = f2tf(qb[(size_t)(ks * 8 + q) * NTOK + iw + g] * qs);
        qa[ks][1] = f2tf(qb[(size_t)(ks * 8 + q) * NTOK + iw + 8 + g] * qs);
        qa[ks][2] = f2tf(qb[(size_t)(ks * 8 + q + 4) * NTOK + iw + g] * qs);
        qa[ks][3] = f2tf(qb[(size_t)(ks * 8 + q + 4) * NTOK + iw + 8 + g] * qs);
    }

    float m0 = NEG_INF, m1 = NEG_INF, l0 = 0.f, l1 = 0.f;
    float oc[4][4];
#pragma unroll
    for (int dn = 0; dn < 4; dn++)
#pragma unroll
        for (int e = 0; e < 4; e++) oc[dn][e] = 0.f;

#define ATTN_STAGE(buf, j0)                                                 \
    {                                                                       \
        _Pragma("unroll")                                                   \
        for (int t = 0; t < 2; t++) {                                       \
            int ch = tid + t * 256;                                         \
            int r = ch >> 4, c4 = (ch & 15) * 4;                            \
            cp16(&Ks[buf][r][c4], &kb[(size_t)r * NTOK + (j0) + c4]);       \
            cp16(&Vs[buf][r][c4], &vb[(size_t)r * NTOK + (j0) + c4]);       \
        }                                                                   \
    }

    ATTN_STAGE(0, 0);
    cp_commit();

    const int njt = NTOK / JT;   // 16
    for (int jt = 0; jt < njt; jt++) {
        const int buf = jt & 1;
        if (jt + 1 < njt) {
            ATTN_STAGE(buf ^ 1, (jt + 1) * JT);
            cp_commit();
            cp_wait<1>();
        } else {
            cp_wait<0>();
        }
        __syncthreads();

        // S = Q K^T (log2 domain): 8 n-tiles of 8 j
        float s[8][4];
#pragma unroll
        for (int nt = 0; nt < 8; nt++) {
            s[nt][0] = 0.f; s[nt][1] = 0.f; s[nt][2] = 0.f; s[nt][3] = 0.f;
#pragma unroll
            for (int ks = 0; ks < 4; ks++) {
                uint32_t b0 = f2tf(Ks[buf][ks * 8 + q][nt * 8 + g]);
                uint32_t b1 = f2tf(Ks[buf][ks * 8 + q + 4][nt * 8 + g]);
                mma_tf32(s[nt], qa[ks], b0, b1);
            }
        }

        // online softmax (base 2)
        float tm0 = NEG_INF, tm1 = NEG_INF;
#pragma unroll
        for (int nt = 0; nt < 8; nt++) {
            tm0 = fmaxf(tm0, fmaxf(s[nt][0], s[nt][1]));
            tm1 = fmaxf(tm1, fmaxf(s[nt][2], s[nt][3]));
        }
        tm0 = fmaxf(tm0, __shfl_xor_sync(0xffffffffu, tm0, 1));
        tm0 = fmaxf(tm0, __shfl_xor_sync(0xffffffffu, tm0, 2));
        tm1 = fmaxf(tm1, __shfl_xor_sync(0xffffffffu, tm1, 1));
        tm1 = fmaxf(tm1, __shfl_xor_sync(0xffffffffu, tm1, 2));

        float mn0 = fmaxf(m0, tm0);
        float mn1 = fmaxf(m1, tm1);
        float al0 = exp2f(m0 - mn0);
        float al1 = exp2f(m1 - mn1);
        m0 = mn0; m1 = mn1;

        float rs0 = 0.f, rs1 = 0.f;
#pragma unroll
        for (int nt = 0; nt < 8; nt++) {
            s[nt][0] = exp2f(s[nt][0] - m0); rs0 += s[nt][0];
            s[nt][1] = exp2f(s[nt][1] - m0); rs0 += s[nt][1];
            s[nt][2] = exp2f(s[nt][2] - m1); rs1 += s[nt][2];
            s[nt][3] = exp2f(s[nt][3] - m1); rs1 += s[nt][3];
        }
        rs0 += __shfl_xor_sync(0xffffffffu, rs0, 1);
        rs0 += __shfl_xor_sync(0xffffffffu, rs0, 2);
        rs1 += __shfl_xor_sync(0xffffffffu, rs1, 1);
        rs1 += __shfl_xor_sync(0xffffffffu, rs1, 2);
        l0 = l0 * al0 + rs0;
        l1 = l1 * al1 + rs1;

#pragma unroll
        for (int dn = 0; dn < 4; dn++) {
            oc[dn][0] *= al0; oc[dn][1] *= al0;
            oc[dn][2] *= al1; oc[dn][3] *= al1;
        }

        // PV (fp16): S C-frags -> P A-frags by direct half2 packing
#pragma unroll
        for (int kc = 0; kc < 4; kc++) {
            uint32_t pa[4];
            pa[0] = packh2(s[2 * kc][0], s[2 * kc][1]);
            pa[1] = packh2(s[2 * kc][2], s[2 * kc][3]);
            pa[2] = packh2(s[2 * kc + 1][0], s[2 * kc + 1][1]);
            pa[3] = packh2(s[2 * kc + 1][2], s[2 * kc + 1][3]);
#pragma unroll
            for (int dn = 0; dn < 4; dn++) {
                float2 v0 = *(const float2*)&Vs[buf][dn * 8 + g][kc * 16 + 2 * q];
                float2 v1 = *(const float2*)&Vs[buf][dn * 8 + g][kc * 16 + 2 * q + 8];
                uint32_t b0 = packh2(v0.x, v0.y);
                uint32_t b1 = packh2(v1.x, v1.y);
                mma_f16(oc[dn], pa, b0, b1);
            }
        }
        __syncthreads();
    }
#undef ATTN_STAGE

    const float inv0 = 1.f / l0;
    const float inv1 = 1.f / l1;
#pragma unroll
    for (int dn = 0; dn < 4; dn++) {
        size_t base = ((size_t)b * DIM + h * DHEAD + dn * 8 + 2 * q) * NTOK;
        O[base + iw + g]            = oc[dn][0] * inv0;
        O[base + NTOK + iw + g]     = oc[dn][1] * inv0;
        O[base + iw + 8 + g]        = oc[dn][2] * inv1;
        O[base + NTOK + iw + 8 + g] = oc[dn][3] * inv1;
    }
}

// ---------------------------------------------------------------------------
// Launch
// ---------------------------------------------------------------------------
extern "C" void kernel_launch(void* const* d_in, const int* in_sizes, int n_in,
                              void* d_out, int out_size)
{
    const float* x = nullptr;
    const float* w_qkv = nullptr;
    const float* w_out = nullptr;
    const float* b_out = nullptr;
    for (int idx = 0; idx < n_in; idx++) {
        switch (in_sizes[idx]) {
            case 2097152: x = (const float*)d_in[idx]; break;
            case 196608:  w_qkv = (const float*)d_in[idx]; break;
            case 65536:   w_out = (const float*)d_in[idx]; break;
            case 256:     b_out = (const float*)d_in[idx]; break;
            default: break;
        }
    }
    float* out = (float*)d_out;

    float* qkvp = nullptr;
    float* op = nullptr;
    cudaGetSymbolAddress((void**)&qkvp, g_qkv);
    cudaGetSymbolAddress((void**)&op, g_o);

    {
        dim3 grid(NTOK / 128, QKV_ROWS / 128, BATCH);
        gemm_tf32_kernel<false><<<grid, 256>>>(w_qkv, x, nullptr, qkvp,
                                               QKV_ROWS, NTOK, DIM);
    }
    {
        dim3 grid(NTOK / 128, NHEADS, BATCH);
        attn_mma_kernel<<<grid, 256>>>(qkvp, op);
    }
    {
        dim3 grid(NTOK / 128, DIM / 128, BATCH);
        gemm_tf32_kernel<true><<<grid, 256>>>(w_out, op, b_out, out,
                                              DIM, NTOK, DIM);
    }
}

// round 8
// speedup vs baseline: 6.9824x; 1.4653x over previous
#include <cuda_runtime.h>
#include <cuda_bf16.h>
#include <cuda_fp16.h>
#include <cstdint>

#define BATCH 8
#define DIM 256
#define NTOK 1024
#define NHEADS 8
#define DHEAD 32
#define QKV_ROWS 768
#define SCALE 0.17677669529663687f
#define LOG2E 1.4426950408889634f
#define NEG_INF __int_as_float(0xff800000)

// fp16 device-global scratch
__device__ __half g_xh[BATCH * DIM * NTOK];        // [b][c][n]
__device__ __half g_wqkvh[QKV_ROWS * DIM];         // [o][c]
__device__ __half g_wouth[DIM * DIM];              // [o][c]
__device__ __half g_qkvh[BATCH * QKV_ROWS * NTOK]; // [b][o][n]
__device__ __half g_oh[BATCH * DIM * NTOK];        // [b][c][n]

// ---------------------------------------------------------------------------
// helpers
// ---------------------------------------------------------------------------
__device__ __forceinline__ void mma_f16(float c[4], const uint32_t a[4],
                                        uint32_t b0, uint32_t b1) {
    asm volatile(
        "mma.sync.aligned.m16n8k16.row.col.f32.f16.f16.f32 "
        "{%0,%1,%2,%3},{%4,%5,%6,%7},{%8,%9},{%0,%1,%2,%3};"
        : "+f"(c[0]), "+f"(c[1]), "+f"(c[2]), "+f"(c[3])
        : "r"(a[0]), "r"(a[1]), "r"(a[2]), "r"(a[3]), "r"(b0), "r"(b1));
}
__device__ __forceinline__ void cp16(void* dst, const void* src) {
    unsigned d = (unsigned)__cvta_generic_to_shared(dst);
    asm volatile("cp.async.cg.shared.global [%0], [%1], 16;" :: "r"(d), "l"(src));
}
__device__ __forceinline__ void cp_commit() { asm volatile("cp.async.commit_group;"); }
template <int N>
__device__ __forceinline__ void cp_wait() {
    asm volatile("cp.async.wait_group %0;" :: "n"(N));
}
// pack two fp32 -> f16x2 (lo -> low half)
__device__ __forceinline__ uint32_t packh2(float lo, float hi) {
    uint32_t r;
    asm("cvt.rn.f16x2.f32 %0, %1, %2;" : "=r"(r) : "f"(hi), "f"(lo));
    return r;
}
__device__ __forceinline__ void ldmx4(uint32_t& d0, uint32_t& d1, uint32_t& d2,
                                      uint32_t& d3, const void* p) {
    unsigned a = (unsigned)__cvta_generic_to_shared(p);
    asm volatile("ldmatrix.sync.aligned.m8n8.x4.shared.b16 {%0,%1,%2,%3}, [%4];"
                 : "=r"(d0), "=r"(d1), "=r"(d2), "=r"(d3) : "r"(a));
}
__device__ __forceinline__ void ldmx4t(uint32_t& d0, uint32_t& d1, uint32_t& d2,
                                       uint32_t& d3, const void* p) {
    unsigned a = (unsigned)__cvta_generic_to_shared(p);
    asm volatile("ldmatrix.sync.aligned.m8n8.x4.trans.shared.b16 {%0,%1,%2,%3}, [%4];"
                 : "=r"(d0), "=r"(d1), "=r"(d2), "=r"(d3) : "r"(a));
}

// ---------------------------------------------------------------------------
// fp32 -> fp16 convert (3 arrays, one launch), float4 -> half4 per thread
// ---------------------------------------------------------------------------
__global__ void convert3_kernel(const float* __restrict__ s0, int q0,
                                const float* __restrict__ s1, int q1,
                                const float* __restrict__ s2, int q2,
                                __half* __restrict__ d0, __half* __restrict__ d1,
                                __half* __restrict__ d2)
{
    int i = blockIdx.x * blockDim.x + threadIdx.x;   // float4 index
    const float* s; __half* d; int j;
    if (i < q0) { s = s0; d = d0; j = i; }
    else if (i < q0 + q1) { s = s1; d = d1; j = i - q0; }
    else if (i < q0 + q1 + q2) { s = s2; d = d2; j = i - q0 - q1; }
    else return;
    float4 v = ((const float4*)s)[j];
    uint2 h;
    h.x = packh2(v.x, v.y);
    h.y = packh2(v.z, v.w);
    *(uint2*)&d[j * 4] = h;
}

// ---------------------------------------------------------------------------
// fp16 GEMM: C[b](MxN) = A(MxK) * B[b](KxN) (+bias). CTA 128x128, kstep 32,
// cp.async double-buffered, ldmatrix operands. 8 warps 4x2, warp tile 32x64.
// HOUT: write fp16 (no bias); else fp32 + bias.
// ---------------------------------------------------------------------------
template <bool BIAS, bool HOUT>
__global__ __launch_bounds__(256, 2) void gemm_f16_kernel(
    const __half* __restrict__ A, const __half* __restrict__ Bg,
    const float* __restrict__ bias, float* __restrict__ Cf,
    __half* __restrict__ Ch, int M, int N, int K)
{
    const __half* B = Bg + (size_t)blockIdx.z * K * N;
    if (HOUT) Ch += (size_t)blockIdx.z * M * N;      // per-batch output offset
    else      Cf += (size_t)blockIdx.z * M * N;
    const int m0 = blockIdx.y * 128;
    const int n0 = blockIdx.x * 128;

    __shared__ __align__(16) __half Ah[2][128][40];   // [m][k] pad 8
    __shared__ __align__(16) __half Bh[2][32][136];   // [k][n] pad 8

    const int tid = threadIdx.x;
    const int lane = tid & 31;
    const int wid = tid >> 5;
    const int wm = wid >> 1;
    const int wn = wid & 1;
    const int g = lane >> 2;
    const int q = lane & 3;
    const int lt = lane >> 3;    // ldmatrix tile id 0..3
    const int lr = lane & 7;     // ldmatrix row-in-tile

    float c[2][8][4];
#pragma unroll
    for (int mt = 0; mt < 2; mt++)
#pragma unroll
        for (int nt = 0; nt < 8; nt++)
#pragma unroll
            for (int e = 0; e < 4; e++) c[mt][nt][e] = 0.f;

    const int nkt = K / 32;

#define GEMM_STAGE(buf, k0)                                                  \
    {                                                                        \
        _Pragma("unroll")                                                    \
        for (int t = 0; t < 2; t++) {                                        \
            int ch = tid + t * 256;                                          \
            int r = ch >> 2, c8 = (ch & 3) * 8;                              \
            cp16(&Ah[buf][r][c8], &A[(size_t)(m0 + r) * K + (k0) + c8]);     \
        }                                                                    \
        _Pragma("unroll")                                                    \
        for (int t = 0; t < 2; t++) {                                        \
            int ch = tid + t * 256;                                          \
            int r = ch >> 4, c8 = (ch & 15) * 8;                             \
            cp16(&Bh[buf][r][c8], &B[(size_t)((k0) + r) * N + n0 + c8]);     \
        }                                                                    \
    }

    GEMM_STAGE(0, 0);
    cp_commit();

    for (int kt = 0; kt < nkt; kt++) {
        const int buf = kt & 1;
        if (kt + 1 < nkt) {
            GEMM_STAGE(buf ^ 1, (kt + 1) * 32);
            cp_commit();
            cp_wait<1>();
        } else {
            cp_wait<0>();
        }
        __syncthreads();

#pragma unroll
        for (int ks = 0; ks < 2; ks++) {
            const int kk = ks * 16;
            uint32_t a[2][4];
#pragma unroll
            for (int mt = 0; mt < 2; mt++) {
                int row = wm * 32 + mt * 16 + (lt & 1) * 8 + lr;
                ldmx4(a[mt][0], a[mt][1], a[mt][2], a[mt][3],
                      &Ah[buf][row][kk + (lt >> 1) * 8]);
            }
#pragma unroll
            for (int p = 0; p < 4; p++) {
                uint32_t b00, b01, b10, b11;
                int brow = kk + (lt & 1) * 8 + lr;
                int bcol = wn * 64 + p * 16 + (lt >> 1) * 8;
                ldmx4t(b00, b01, b10, b11, &Bh[buf][brow][bcol]);
                mma_f16(c[0][2 * p], a[0], b00, b01);
                mma_f16(c[1][2 * p], a[1], b00, b01);
                mma_f16(c[0][2 * p + 1], a[0], b10, b11);
                mma_f16(c[1][2 * p + 1], a[1], b10, b11);
            }
        }
        __syncthreads();
    }
#undef GEMM_STAGE

#pragma unroll
    for (int mt = 0; mt < 2; mt++) {
        int row = m0 + wm * 32 + mt * 16 + g;
#pragma unroll
        for (int nt = 0; nt < 8; nt++) {
            int col = n0 + wn * 64 + nt * 8 + 2 * q;
            if (HOUT) {
                *(uint32_t*)&Ch[(size_t)row * N + col] =
                    packh2(c[mt][nt][0], c[mt][nt][1]);
                *(uint32_t*)&Ch[(size_t)(row + 8) * N + col] =
                    packh2(c[mt][nt][2], c[mt][nt][3]);
            } else {
                float bv0 = BIAS ? bias[row] : 0.f;
                float bv8 = BIAS ? bias[row + 8] : 0.f;
                float2 lo = make_float2(c[mt][nt][0] + bv0, c[mt][nt][1] + bv0);
                float2 hi = make_float2(c[mt][nt][2] + bv8, c[mt][nt][3] + bv8);
                *(float2*)&Cf[(size_t)row * N + col] = lo;
                *(float2*)&Cf[(size_t)(row + 8) * N + col] = hi;
            }
        }
    }
}

// ---------------------------------------------------------------------------
// Flash attention, fp16 mma everywhere (fp32 accum + fp32 softmax).
// CTA = (128-query tile, head, batch), 8 warps x 16 queries. j-tiles of 64,
// K/V fp16 double-buffered via cp.async, [d][j] layout (pad 72).
// S: A=Q (regs), B=K^T via ldmatrix.trans. PV: A=P (packed from S C-frags),
// B=V^T via plain ldmatrix on [d][j] (= n-major) layout.
// ---------------------------------------------------------------------------
#define JT 64

__global__ __launch_bounds__(256, 2) void attn_mma_kernel(
    const __half* __restrict__ qkv, __half* __restrict__ O)
{
    const int b = blockIdx.z;
    const int h = blockIdx.y;

    const __half* qb = qkv + ((size_t)b * QKV_ROWS + h * DHEAD) * NTOK;
    const __half* kb = qb + (size_t)256 * NTOK;
    const __half* vb = qb + (size_t)512 * NTOK;

    __shared__ __align__(16) __half Ks[2][32][72];
    __shared__ __align__(16) __half Vs[2][32][72];

    const int tid = threadIdx.x;
    const int lane = tid & 31;
    const int wid = tid >> 5;
    const int g = lane >> 2;
    const int q = lane & 3;
    const int lt = lane >> 3;
    const int lr = lane & 7;
    const int iw = blockIdx.x * 128 + wid * 16;

    // Q fragments (A, 16 queries x 32 d), prescaled into log2 domain
    const float qs = SCALE * LOG2E;
    uint32_t qa[2][4];
#pragma unroll
    for (int ks = 0; ks < 2; ks++) {
        const int kd = ks * 16;
#pragma unroll
        for (int half8 = 0; half8 < 2; half8++) {
            int d0 = kd + half8 * 8 + 2 * q;
            float a0 = __half2float(qb[(size_t)d0 * NTOK + iw + g]) * qs;
            float a1 = __half2float(qb[(size_t)(d0 + 1) * NTOK + iw + g]) * qs;
            float b0 = __half2float(qb[(size_t)d0 * NTOK + iw + 8 + g]) * qs;
            float b1 = __half2float(qb[(size_t)(d0 + 1) * NTOK + iw + 8 + g]) * qs;
            qa[ks][2 * half8]     = packh2(a0, a1);
            qa[ks][2 * half8 + 1] = packh2(b0, b1);
        }
    }

    float m0 = NEG_INF, m1 = NEG_INF, l0 = 0.f, l1 = 0.f;
    float oc[4][4];
#pragma unroll
    for (int dn = 0; dn < 4; dn++)
#pragma unroll
        for (int e = 0; e < 4; e++) oc[dn][e] = 0.f;

#define ATTN_STAGE(buf, j0)                                                 \
    {                                                                       \
        int r = tid >> 3, c8 = (tid & 7) * 8;                               \
        cp16(&Ks[buf][r][c8], &kb[(size_t)r * NTOK + (j0) + c8]);           \
        cp16(&Vs[buf][r][c8], &vb[(size_t)r * NTOK + (j0) + c8]);           \
    }

    ATTN_STAGE(0, 0);
    cp_commit();

    const int njt = NTOK / JT;   // 16
    for (int jt = 0; jt < njt; jt++) {
        const int buf = jt & 1;
        if (jt + 1 < njt) {
            ATTN_STAGE(buf ^ 1, (jt + 1) * JT);
            cp_commit();
            cp_wait<1>();
        } else {
            cp_wait<0>();
        }
        __syncthreads();

        // S = Q K^T (log2 domain): 8 n-tiles of 8 j
        float s[8][4];
#pragma unroll
        for (int nt = 0; nt < 8; nt++) {
            s[nt][0] = 0.f; s[nt][1] = 0.f; s[nt][2] = 0.f; s[nt][3] = 0.f;
        }
#pragma unroll
        for (int p = 0; p < 4; p++) {
#pragma unroll
            for (int ks = 0; ks < 2; ks++) {
                uint32_t b00, b01, b10, b11;
                int brow = ks * 16 + (lt & 1) * 8 + lr;
                int bcol = p * 16 + (lt >> 1) * 8;
                ldmx4t(b00, b01, b10, b11, &Ks[buf][brow][bcol]);
                mma_f16(s[2 * p], qa[ks], b00, b01);
                mma_f16(s[2 * p + 1], qa[ks], b10, b11);
            }
        }

        // online softmax (base 2)
        float tm0 = NEG_INF, tm1 = NEG_INF;
#pragma unroll
        for (int nt = 0; nt < 8; nt++) {
            tm0 = fmaxf(tm0, fmaxf(s[nt][0], s[nt][1]));
            tm1 = fmaxf(tm1, fmaxf(s[nt][2], s[nt][3]));
        }
        tm0 = fmaxf(tm0, __shfl_xor_sync(0xffffffffu, tm0, 1));
        tm0 = fmaxf(tm0, __shfl_xor_sync(0xffffffffu, tm0, 2));
        tm1 = fmaxf(tm1, __shfl_xor_sync(0xffffffffu, tm1, 1));
        tm1 = fmaxf(tm1, __shfl_xor_sync(0xffffffffu, tm1, 2));

        float mn0 = fmaxf(m0, tm0);
        float mn1 = fmaxf(m1, tm1);
        float al0 = exp2f(m0 - mn0);
        float al1 = exp2f(m1 - mn1);
        m0 = mn0; m1 = mn1;

        float rs0 = 0.f, rs1 = 0.f;
#pragma unroll
        for (int nt = 0; nt < 8; nt++) {
            s[nt][0] = exp2f(s[nt][0] - m0); rs0 += s[nt][0];
            s[nt][1] = exp2f(s[nt][1] - m0); rs0 += s[nt][1];
            s[nt][2] = exp2f(s[nt][2] - m1); rs1 += s[nt][2];
            s[nt][3] = exp2f(s[nt][3] - m1); rs1 += s[nt][3];
        }
        rs0 += __shfl_xor_sync(0xffffffffu, rs0, 1);
        rs0 += __shfl_xor_sync(0xffffffffu, rs0, 2);
        rs1 += __shfl_xor_sync(0xffffffffu, rs1, 1);
        rs1 += __shfl_xor_sync(0xffffffffu, rs1, 2);
        l0 = l0 * al0 + rs0;
        l1 = l1 * al1 + rs1;

#pragma unroll
        for (int dn = 0; dn < 4; dn++) {
            oc[dn][0] *= al0; oc[dn][1] *= al0;
            oc[dn][2] *= al1; oc[dn][3] *= al1;
        }

        // PV: A = P (from S C-frags), B = V^T via plain ldmatrix on [d][j]
#pragma unroll
        for (int kc = 0; kc < 4; kc++) {
            uint32_t pa[4];
            pa[0] = packh2(s[2 * kc][0], s[2 * kc][1]);
            pa[1] = packh2(s[2 * kc][2], s[2 * kc][3]);
            pa[2] = packh2(s[2 * kc + 1][0], s[2 * kc + 1][1]);
            pa[3] = packh2(s[2 * kc + 1][2], s[2 * kc + 1][3]);
#pragma unroll
            for (int dnp = 0; dnp < 2; dnp++) {
                uint32_t b0a, b1a, b0b, b1b;
                int vrow = dnp * 16 + (lt >> 1) * 8 + lr;
                int vcol = kc * 16 + (lt & 1) * 8;
                ldmx4(b0a, b1a, b0b, b1b, &Vs[buf][vrow][vcol]);
                mma_f16(oc[2 * dnp], pa, b0a, b1a);
                mma_f16(oc[2 * dnp + 1], pa, b0b, b1b);
            }
        }
        __syncthreads();
    }
#undef ATTN_STAGE

    const float inv0 = 1.f / l0;
    const float inv1 = 1.f / l1;
#pragma unroll
    for (int dn = 0; dn < 4; dn++) {
        size_t base = ((size_t)b * DIM + h * DHEAD + dn * 8 + 2 * q) * NTOK;
        O[base + iw + g]            = __float2half(oc[dn][0] * inv0);
        O[base + NTOK + iw + g]     = __float2half(oc[dn][1] * inv0);
        O[base + iw + 8 + g]        = __float2half(oc[dn][2] * inv1);
        O[base + NTOK + iw + 8 + g] = __float2half(oc[dn][3] * inv1);
    }
}

// ---------------------------------------------------------------------------
// Launch
// ---------------------------------------------------------------------------
extern "C" void kernel_launch(void* const* d_in, const int* in_sizes, int n_in,
                              void* d_out, int out_size)
{
    const float* x = nullptr;
    const float* w_qkv = nullptr;
    const float* w_out = nullptr;
    const float* b_out = nullptr;
    for (int idx = 0; idx < n_in; idx++) {
        switch (in_sizes[idx]) {
            case 2097152: x = (const float*)d_in[idx]; break;
            case 196608:  w_qkv = (const float*)d_in[idx]; break;
            case 65536:   w_out = (const float*)d_in[idx]; break;
            case 256:     b_out = (const float*)d_in[idx]; break;
            default: break;
        }
    }
    float* out = (float*)d_out;

    __half *xh, *wqkvh, *wouth, *qkvh, *oh;
    cudaGetSymbolAddress((void**)&xh, g_xh);
    cudaGetSymbolAddress((void**)&wqkvh, g_wqkvh);
    cudaGetSymbolAddress((void**)&wouth, g_wouth);
    cudaGetSymbolAddress((void**)&qkvh, g_qkvh);
    cudaGetSymbolAddress((void**)&oh, g_oh);

    // 0) convert inputs to fp16
    {
        int q0 = 2097152 / 4, q1 = 196608 / 4, q2 = 65536 / 4;
        int total = q0 + q1 + q2;
        convert3_kernel<<<(total + 255) / 256, 256>>>(x, q0, w_qkv, q1, w_out, q2,
                                                      xh, wqkvh, wouth);
    }
    // 1) QKV projection (fp16 in/out)
    {
        dim3 grid(NTOK / 128, QKV_ROWS / 128, BATCH);
        gemm_f16_kernel<false, true><<<grid, 256>>>(wqkvh, xh, nullptr, nullptr,
                                                    qkvh, QKV_ROWS, NTOK, DIM);
    }
    // 2) Fused flash attention (fp16 mma)
    {
        dim3 grid(NTOK / 128, NHEADS, BATCH);
        attn_mma_kernel<<<grid, 256>>>(qkvh, oh);
    }
    // 3) Output projection + bias (fp16 in, fp32 out)
    {
        dim3 grid(NTOK / 128, DIM / 128, BATCH);
        gemm_f16_kernel<true, false><<<grid, 256>>>(wouth, oh, b_out, out,
                                                    nullptr, DIM, NTOK, DIM);
    }
}